// round 5
// baseline (speedup 1.0000x reference)
#include <cuda_runtime.h>
#include <math.h>

// Causal depthwise conv1d, K=24, T=3000.
// y[b,c,t] = sum_{k=0..23} w[c,k] * x[b,c,t-23+k]
// w[c,k] = beta*exp(log(max(alpha,1e-6))*k)*(1 - u^2/2 + u^4/24), u=theta*k
//
// R5: packed fma.rn.f32x2 over the OUTPUT dimension:
//   acc2[p] = (y[2p], y[2p+1]) = sum_k (w[k],w[k]) (x) (X[2p+1+k], X[2p+2+k])
//   k even -> odd-aligned pair O[p+k/2]; k odd -> aligned pair X.u[p+(k+1)/2]
//   Epilogue is free: acc2 pairs are stored directly (no horizontal sum).

#define KSZ 24
#define T_LEN 3000
#define R_OUT 12
#define NPAIR (R_OUT / 2)      // 6 packed accumulators
#define NACT (T_LEN / R_OUT)   // 250 active compute threads
#define NTHREADS 256
#define NVEC (T_LEN / 4)       // 750 float4 per row

__device__ __forceinline__ unsigned long long pk2(float lo, float hi) {
    unsigned long long d;
    asm("mov.b64 %0, {%1, %2};" : "=l"(d) : "f"(lo), "f"(hi));
    return d;
}
__device__ __forceinline__ unsigned long long fma2(unsigned long long a,
                                                   unsigned long long b,
                                                   unsigned long long c) {
    unsigned long long d;
    asm("fma.rn.f32x2 %0, %1, %2, %3;" : "=l"(d) : "l"(a), "l"(b), "l"(c));
    return d;
}

__global__ __launch_bounds__(NTHREADS)
void ssm4d_conv_kernel(const float* __restrict__ x,
                       const float* __restrict__ alpha,
                       const float* __restrict__ beta,
                       const float* __restrict__ theta,
                       float* __restrict__ y,
                       int C)
{
    // S[0..23]  = zeros (24-wide pad keeps all STS.128 aligned)
    // S[24 + t] = x[row, t]
    // Identity: y[t] = sum_k w[k] * S[t + 1 + k]
    __shared__ __align__(16) float S[KSZ + T_LEN];   // 3024 floats
    __shared__ __align__(16) float sw2[2 * KSZ];     // duplicated pairs (w,w)

    const int c   = blockIdx.x;
    const int b   = blockIdx.y;
    const int tid = threadIdx.x;
    const long rowbase = ((long)b * C + c) * (long)T_LEN;

    // ---- fill: aligned LDG.128 -> STS.128 ----
    const float4* xv = reinterpret_cast<const float4*>(x + rowbase);
    float4*       Sd = reinterpret_cast<float4*>(S + KSZ);
#pragma unroll
    for (int i = tid; i < NVEC; i += NTHREADS) Sd[i] = xv[i];
    if (tid < KSZ / 4)
        reinterpret_cast<float4*>(S)[tid] = make_float4(0.f, 0.f, 0.f, 0.f);

    // ---- per-channel weights, stored duplicated: sw2[2k]=sw2[2k+1]=w[k] ----
    if (tid < KSZ) {
        float a  = alpha[c];
        float la = logf(fmaxf(a, 1e-6f));
        float d  = expf(la * (float)tid);
        float u  = theta[c] * (float)tid;
        float u2 = u * u;
        float ph = 1.0f - 0.5f * u2 + (u2 * u2) * (1.0f / 24.0f);
        float wv = beta[c] * d * ph;
        sw2[2 * tid]     = wv;
        sw2[2 * tid + 1] = wv;
    }
    __syncthreads();

    if (tid < NACT) {
        // window: X[0..35] = S[12*tid .. 12*tid+35]
        // 9 LDS.128, lane stride 48B -> conflict-free.
        union {
            float4             v4[9];
            unsigned long long u[18];
            float              f[36];
        } X;
        const float4* S4 = reinterpret_cast<const float4*>(&S[R_OUT * tid]);
#pragma unroll
        for (int j = 0; j < 9; j++) X.v4[j] = S4[j];

        // odd-aligned pairs O[m] = (X[2m+1], X[2m+2]), m = 0..16
        unsigned long long O[17];
#pragma unroll
        for (int m = 0; m < 17; m++) O[m] = pk2(X.f[2 * m + 1], X.f[2 * m + 2]);

        union {
            unsigned long long a2[NPAIR];
            float4             v4[3];
        } acc;
#pragma unroll
        for (int p = 0; p < NPAIR; p++) acc.a2[p] = 0ull;

        const unsigned long long* w2 =
            reinterpret_cast<const unsigned long long*>(sw2);
#pragma unroll
        for (int e = 0; e < 12; e++) {
            // k = 2e   (even): operand O[p+e]
            unsigned long long we = w2[2 * e];        // broadcast LDS.64
#pragma unroll
            for (int p = 0; p < NPAIR; p++)
                acc.a2[p] = fma2(we, O[p + e], acc.a2[p]);
            // k = 2e+1 (odd): operand X.u[p+e+1]
            unsigned long long wo = w2[2 * e + 1];    // broadcast LDS.64
#pragma unroll
            for (int p = 0; p < NPAIR; p++)
                acc.a2[p] = fma2(wo, X.u[p + e + 1], acc.a2[p]);
        }

        // store 12 outputs: 3 aligned STG.128 (pairs are already in order)
        float4* yo = reinterpret_cast<float4*>(y + rowbase + R_OUT * tid);
#pragma unroll
        for (int j = 0; j < 3; j++) yo[j] = acc.v4[j];
    }
}

extern "C" void kernel_launch(void* const* d_in, const int* in_sizes, int n_in,
                              void* d_out, int out_size)
{
    const float* x     = (const float*)d_in[0];
    const float* alpha = (const float*)d_in[1];
    const float* beta  = (const float*)d_in[2];
    const float* theta = (const float*)d_in[3];
    float* y = (float*)d_out;

    const int C = in_sizes[1];                 // 1024
    const int B = in_sizes[0] / (C * T_LEN);   // 16

    dim3 grid(C, B);
    ssm4d_conv_kernel<<<grid, NTHREADS>>>(x, alpha, beta, theta, y, C);
}

// round 6
// speedup vs baseline: 1.2048x; 1.2048x over previous
#include <cuda_runtime.h>
#include <math.h>
#include <stdint.h>

// Causal depthwise conv1d, K=24, T=3000.
// y[b,c,t] = sum_{k=0..23} w[c,k] * x[b,c,t-23+k]
// w[c,k] = beta*exp(log(max(alpha,1e-6))*k)*(1 - u^2/2 + u^4/24), u=theta*k
//
// R6: R4 compute core (scalar FFMA, R=12, conflict-free 48B-stride LDS.128)
//     + TMA bulk fill (cp.async.bulk -> smem, no LDG/STS/regs in fill)
//     + occupancy 7 CTAs/SM.

#define KSZ 24
#define T_LEN 3000
#define R_OUT 12
#define NACT (T_LEN / R_OUT)   // 250 active compute threads
#define NTHREADS 256
#define PAD 24                 // zero pad floats (16B-aligned TMA dst after pad)
#define ROW_BYTES (T_LEN * 4)  // 12000, 16B-multiple

__global__ __launch_bounds__(NTHREADS, 7)
void ssm4d_conv_kernel(const float* __restrict__ x,
                       const float* __restrict__ alpha,
                       const float* __restrict__ beta,
                       const float* __restrict__ theta,
                       float* __restrict__ y,
                       int C)
{
    // S[0..23]  = zeros; S[24+t] = x[row,t];  y[t] = sum_k w[k]*S[t+1+k]
    __shared__ __align__(16) float S[PAD + T_LEN];
    __shared__ __align__(16) float sw[KSZ];
    __shared__ __align__(8)  unsigned long long mbar;

    const int c   = blockIdx.x;
    const int b   = blockIdx.y;
    const int tid = threadIdx.x;
    const long rowbase = ((long)b * C + c) * (long)T_LEN;

    const uint32_t mba  = (uint32_t)__cvta_generic_to_shared(&mbar);
    const uint32_t sdst = (uint32_t)__cvta_generic_to_shared(S + PAD);

    if (tid == 0)
        asm volatile("mbarrier.init.shared.b64 [%0], 1;" :: "r"(mba) : "memory");
    __syncthreads();

    if (tid == 0) {
        asm volatile("mbarrier.arrive.expect_tx.shared.b64 _, [%0], %1;"
                     :: "r"(mba), "r"((uint32_t)ROW_BYTES) : "memory");
        asm volatile(
            "cp.async.bulk.shared::cluster.global.mbarrier::complete_tx::bytes "
            "[%0], [%1], %2, [%3];"
            :: "r"(sdst), "l"(x + rowbase), "r"((uint32_t)ROW_BYTES), "r"(mba)
            : "memory");
    }

    // overlap with the TMA flight: zero pad + per-channel weights
    if (tid < PAD / 4)
        reinterpret_cast<float4*>(S)[tid] = make_float4(0.f, 0.f, 0.f, 0.f);
    if (tid < KSZ) {
        float a  = alpha[c];
        float la = logf(fmaxf(a, 1e-6f));
        float d  = expf(la * (float)tid);
        float u  = theta[c] * (float)tid;
        float u2 = u * u;
        float ph = 1.0f - 0.5f * u2 + (u2 * u2) * (1.0f / 24.0f);
        sw[tid] = beta[c] * d * ph;
    }
    __syncthreads();   // pad + weights visible to all

    // wait for TMA completion (phase 0), acquire for subsequent LDS
    {
        uint32_t done;
        asm volatile(
            "{\n\t"
            ".reg .pred p;\n\t"
            "mbarrier.try_wait.parity.acquire.cta.shared::cta.b64 p, [%1], %2;\n\t"
            "selp.b32 %0, 1, 0, p;\n\t"
            "}"
            : "=r"(done) : "r"(mba), "r"(0u) : "memory");
        if (!done) {
            asm volatile(
                "{\n\t"
                ".reg .pred P1;\n\t"
                "WAIT_LOOP:\n\t"
                "mbarrier.try_wait.parity.acquire.cta.shared::cta.b64 P1, [%0], %1, 0x989680;\n\t"
                "@P1 bra.uni WAIT_DONE;\n\t"
                "bra.uni WAIT_LOOP;\n\t"
                "WAIT_DONE:\n\t"
                "}"
                :: "r"(mba), "r"(0u) : "memory");
        }
    }

    if (tid < NACT) {
        // weights: 6 broadcast LDS.128
        float w[KSZ];
#pragma unroll
        for (int j = 0; j < KSZ / 4; j++) {
            float4 wv = reinterpret_cast<const float4*>(sw)[j];
            w[4 * j + 0] = wv.x; w[4 * j + 1] = wv.y;
            w[4 * j + 2] = wv.z; w[4 * j + 3] = wv.w;
        }

        // window: X[0..35] = S[12*tid .. 12*tid+35]
        // 9 LDS.128, lane stride 48B -> conflict-free.
        float X[R_OUT + KSZ];   // 36
        const float4* S4 = reinterpret_cast<const float4*>(&S[R_OUT * tid]);
#pragma unroll
        for (int j = 0; j < 9; j++) {
            float4 v = S4[j];
            X[4 * j + 0] = v.x; X[4 * j + 1] = v.y;
            X[4 * j + 2] = v.z; X[4 * j + 3] = v.w;
        }

        // y[12*tid + j] = sum_k w[k] * X[j + 1 + k]
        float acc[R_OUT];
#pragma unroll
        for (int j = 0; j < R_OUT; j++) acc[j] = 0.0f;
#pragma unroll
        for (int k = 0; k < KSZ; k++) {
            float wk = w[k];
#pragma unroll
            for (int j = 0; j < R_OUT; j++)
                acc[j] = fmaf(wk, X[j + 1 + k], acc[j]);
        }

        // 12 outputs: 3 aligned STG.128
        float4* yo = reinterpret_cast<float4*>(y + rowbase + R_OUT * tid);
#pragma unroll
        for (int j = 0; j < 3; j++) {
            float4 o;
            o.x = acc[4 * j + 0]; o.y = acc[4 * j + 1];
            o.z = acc[4 * j + 2]; o.w = acc[4 * j + 3];
            yo[j] = o;
        }
    }
}

extern "C" void kernel_launch(void* const* d_in, const int* in_sizes, int n_in,
                              void* d_out, int out_size)
{
    const float* x     = (const float*)d_in[0];
    const float* alpha = (const float*)d_in[1];
    const float* beta  = (const float*)d_in[2];
    const float* theta = (const float*)d_in[3];
    float* y = (float*)d_out;

    const int C = in_sizes[1];                 // 1024
    const int B = in_sizes[0] / (C * T_LEN);   // 16

    dim3 grid(C, B);
    ssm4d_conv_kernel<<<grid, NTHREADS>>>(x, alpha, beta, theta, y, C);
}